// round 9
// baseline (speedup 1.0000x reference)
#include <cuda_runtime.h>
#include <cuda_fp16.h>
#include <math.h>

#define N_NODES 100000
#define E_EDGES 1600000
#define G_GR    2000
#define P_PAIRS 4096
#define UDIM    128
#define HSTRIDE 136
#define NCHUNK  4

// ---------------- scratch (static device globals; no allocation) -------------
// Globals start zeroed; each run re-zeroes what it dirties (d_counts in
// k_final, d_gsum/d_gcnt in k_util) so graph replays stay deterministic.
__device__ __half d_b0[N_NODES * UDIM];    // buffer A
__device__ __half d_b1[N_NODES * UDIM];    // buffer B
__device__ __half d_b2[N_NODES * UDIM];    // buffer C
__device__ __half d_wh[3 * 128 * HSTRIDE]; // pre-transposed fp16 weights (n,k)
__device__ int    d_counts[N_NODES];
__device__ int    d_startA[N_NODES];
__device__ int    d_cursor[N_NODES];
__device__ int    d_bsums[128];
__device__ float  d_dinv[N_NODES];
__device__ int    d_esrc[E_EDGES];         // edge srcs sorted by dst
__device__ float  d_gsum[G_GR];
__device__ int    d_gcnt[G_GR];
__device__ float  d_util[G_GR];

// ---------------- helpers ----------------------------------------------------
__device__ __forceinline__ float4 h4_to_f4(uint2 u) {
    __half2 p0 = *(__half2*)&u.x;
    __half2 p1 = *(__half2*)&u.y;
    float2 f0 = __half22float2(p0), f1 = __half22float2(p1);
    return make_float4(f0.x, f0.y, f1.x, f1.y);
}
__device__ __forceinline__ void add_f4(float4& a, uint2 u) {
    float2 x = __half22float2(*(__half2*)&u.x);
    float2 y = __half22float2(*(__half2*)&u.y);
    a.x += x.x; a.y += x.y; a.z += y.x; a.w += y.y;
}
__device__ __forceinline__ void fma_f4(float4& a, uint2 u, float s) {
    float2 x = __half22float2(*(__half2*)&u.x);
    float2 y = __half22float2(*(__half2*)&u.y);
    a.x = fmaf(s, x.x, a.x); a.y = fmaf(s, x.y, a.y);
    a.z = fmaf(s, y.x, a.z); a.w = fmaf(s, y.y, a.w);
}

// ---------------- CSR build --------------------------------------------------
__global__ void k_count(const int* __restrict__ ei) {
    int e = blockIdx.x * blockDim.x + threadIdx.x;
    if (e < E_EDGES / 4) {
        int4 d4 = __ldg((const int4*)(ei + E_EDGES) + e);
        atomicAdd(&d_counts[d4.x], 1);
        atomicAdd(&d_counts[d4.y], 1);
        atomicAdd(&d_counts[d4.z], 1);
        atomicAdd(&d_counts[d4.w], 1);
    }
}

__global__ void k_scan1(int n) {
    __shared__ int wsum[32];
    int i = blockIdx.x * 1024 + threadIdx.x;
    int lane = threadIdx.x & 31, w = threadIdx.x >> 5;
    int v = (i < n) ? d_counts[i] : 0;
    int x = v;
#pragma unroll
    for (int o = 1; o < 32; o <<= 1) {
        int y = __shfl_up_sync(0xffffffffu, x, o);
        if (lane >= o) x += y;
    }
    if (lane == 31) wsum[w] = x;
    __syncthreads();
    if (w == 0) {
        int s = wsum[lane];
        int xx = s;
#pragma unroll
        for (int o = 1; o < 32; o <<= 1) {
            int y = __shfl_up_sync(0xffffffffu, xx, o);
            if (lane >= o) xx += y;
        }
        if (lane == 31) d_bsums[blockIdx.x] = xx;
        wsum[lane] = xx - s;
    }
    __syncthreads();
    int excl = x - v + wsum[w];
    if (i < n) d_startA[i] = excl;
}

__global__ void k_scan3(const int* __restrict__ batch) {
    __shared__ int soff;
    int i = blockIdx.x * 256 + threadIdx.x;
    int tile = (blockIdx.x * 256) >> 10;
    if (threadIdx.x < 32) {
        int lane = threadIdx.x;
        int s = 0;
        for (int j = lane; j < tile; j += 32) s += d_bsums[j];
#pragma unroll
        for (int o = 16; o > 0; o >>= 1) s += __shfl_xor_sync(0xffffffffu, s, o);
        if (lane == 0) soff = s;
    }
    __syncthreads();
    if (i < N_NODES) {
        int sA = d_startA[i] + soff;
        d_startA[i] = sA;
        d_cursor[i] = sA;
        d_dinv[i] = rsqrtf((float)d_counts[i] + 1.0f);
        atomicAdd(&d_gcnt[__ldg(&batch[i])], 1);
    }
}

__global__ void k_fill(const int* __restrict__ ei) {
    int e = blockIdx.x * blockDim.x + threadIdx.x;
    if (e < E_EDGES / 4) {
        int4 s4 = __ldg((const int4*)ei + e);
        int4 t4 = __ldg((const int4*)(ei + E_EDGES) + e);
        d_esrc[atomicAdd(&d_cursor[t4.x], 1)] = s4.x;
        d_esrc[atomicAdd(&d_cursor[t4.y], 1)] = s4.y;
        d_esrc[atomicAdd(&d_cursor[t4.z], 1)] = s4.z;
        d_esrc[atomicAdd(&d_cursor[t4.w], 1)] = s4.w;
    }
}

// pre-transpose three 128x128 fp32 weights -> fp16 (n,k) padded HSTRIDE
__global__ void k_prepw(const float* __restrict__ W0, const float* __restrict__ W1,
                        const float* __restrict__ W2) {
    int tid = blockIdx.x * blockDim.x + threadIdx.x;
    if (tid >= 3 * 16384) return;
    int m = tid >> 14, r = tid & 16383;
    int k = r >> 7, n = r & 127;
    const float* W = (m == 0) ? W0 : (m == 1) ? W1 : W2;
    d_wh[m * 128 * HSTRIDE + n * HSTRIDE + k] = __float2half(W[k * 128 + n]);
}

// ---------------- GEMMs -----------------------------------------------------
// layer 0: y = x[N,9] @ W_in[9,128] (raw, no dinv) -> fp16
__global__ void k_gemm_in(const float* __restrict__ x, const float* __restrict__ W,
                          __half* __restrict__ g) {
    __shared__ float Ws[9 * 128];
    for (int i = threadIdx.x; i < 9 * 128; i += 128) Ws[i] = W[i];
    __syncthreads();
    int j = threadIdx.x;
    for (int row = blockIdx.x; row < N_NODES; row += gridDim.x) {
        float acc = 0.0f;
#pragma unroll
        for (int k = 0; k < 9; k++)
            acc += __ldg(&x[row * 9 + k]) * Ws[k * 128 + j];
        g[row * 128 + j] = __float2half(acc);
    }
}

// fp16 TC GEMM over one node chunk. MODE 0: C = dinv*(A@W)  MODE 1: C = tanh(A@W+bias)
template <int MODE>
__global__ __launch_bounds__(256) void k_gemm_tc(
        const __half* __restrict__ A, const __half* __restrict__ Wt_g,
        const float* __restrict__ bias, __half* __restrict__ C, int row_base) {
    extern __shared__ __half sm[];
    __half* As = sm;                  // [128][136] (row, k)
    __half* Wt = sm + 128 * HSTRIDE;  // [128][136] (n, k)
    const int t = threadIdx.x;
    const int row0 = row_base + blockIdx.x * 128;

    const uint4* Wg4 = (const uint4*)Wt_g;
    uint4* Wt4 = (uint4*)Wt;
    for (int i = t; i < 128 * 17; i += 256) Wt4[i] = Wg4[i];

    const uint4* A4 = (const uint4*)A;
    for (int i = t; i < 128 * 16; i += 256) {
        int r = i >> 4, c = i & 15;
        uint4 v = make_uint4(0u, 0u, 0u, 0u);
        if (row0 + r < N_NODES) v = A4[(size_t)(row0 + r) * 16 + c];
        *(uint4*)&As[r * HSTRIDE + c * 8] = v;
    }
    __syncthreads();

    const int w = t >> 5, lane = t & 31;
    const int wm = w & 3, wn = w >> 2;
    const int rbase = wm * 32;
    const int cbase = wn * 64;
    const int gid = lane >> 2, tig = lane & 3;

    float acc[2][8][4];
#pragma unroll
    for (int mi = 0; mi < 2; mi++)
#pragma unroll
        for (int ni = 0; ni < 8; ni++)
#pragma unroll
            for (int q = 0; q < 4; q++) acc[mi][ni][q] = 0.0f;

#pragma unroll
    for (int ks = 0; ks < 8; ks++) {
        const int k0 = ks * 16;
        unsigned a[2][4];
#pragma unroll
        for (int mi = 0; mi < 2; mi++) {
            int r = rbase + mi * 16 + gid;
            a[mi][0] = *(const unsigned*)&As[r * HSTRIDE + k0 + tig * 2];
            a[mi][1] = *(const unsigned*)&As[(r + 8) * HSTRIDE + k0 + tig * 2];
            a[mi][2] = *(const unsigned*)&As[r * HSTRIDE + k0 + 8 + tig * 2];
            a[mi][3] = *(const unsigned*)&As[(r + 8) * HSTRIDE + k0 + 8 + tig * 2];
        }
        unsigned b[8][2];
#pragma unroll
        for (int ni = 0; ni < 8; ni++) {
            int n = cbase + ni * 8 + gid;
            b[ni][0] = *(const unsigned*)&Wt[n * HSTRIDE + k0 + tig * 2];
            b[ni][1] = *(const unsigned*)&Wt[n * HSTRIDE + k0 + 8 + tig * 2];
        }
#pragma unroll
        for (int mi = 0; mi < 2; mi++)
#pragma unroll
            for (int ni = 0; ni < 8; ni++)
                asm volatile(
                    "mma.sync.aligned.m16n8k16.row.col.f32.f16.f16.f32 "
                    "{%0,%1,%2,%3}, {%4,%5,%6,%7}, {%8,%9}, {%0,%1,%2,%3};"
                    : "+f"(acc[mi][ni][0]), "+f"(acc[mi][ni][1]),
                      "+f"(acc[mi][ni][2]), "+f"(acc[mi][ni][3])
                    : "r"(a[mi][0]), "r"(a[mi][1]), "r"(a[mi][2]), "r"(a[mi][3]),
                      "r"(b[ni][0]), "r"(b[ni][1]));
    }

#pragma unroll
    for (int mi = 0; mi < 2; mi++) {
#pragma unroll
        for (int hf = 0; hf < 2; hf++) {
            int r = row0 + rbase + mi * 16 + gid + hf * 8;
            if (r < N_NODES) {
                float scale = (MODE == 0) ? d_dinv[r] : 1.0f;
#pragma unroll
                for (int ni = 0; ni < 8; ni++) {
                    int c = cbase + ni * 8 + tig * 2;
                    float v0 = acc[mi][ni][hf * 2 + 0];
                    float v1 = acc[mi][ni][hf * 2 + 1];
                    if (MODE == 0) { v0 *= scale; v1 *= scale; }
                    else {
                        v0 = tanhf(v0 + __ldg(&bias[c]));
                        v1 = tanhf(v1 + __ldg(&bias[c + 1]));
                    }
                    *(__half2*)&C[(size_t)r * 128 + c] = __floats2half2_rn(v0, v1);
                }
            }
        }
    }
}

// ---------------- edge aggregation ------------------------------------------
// Variant A (layer 0, raw y in gbuf): h = tanh(dinv_d*(dinv_d*y_d + sum dinv_s*y_s)+b)
__global__ void k_aggA(const __half* __restrict__ gbuf, const float* __restrict__ bias,
                       __half* __restrict__ hout, int base, int nn) {
    int d = base + ((blockIdx.x * blockDim.x + threadIdx.x) >> 5);
    if (d >= base + nn || d >= N_NODES) return;
    int lane = threadIdx.x & 31;

    const uint2* g2 = (const uint2*)gbuf;
    float dself = d_dinv[d];
    float4 acc = make_float4(0.f, 0.f, 0.f, 0.f);
    fma_f4(acc, __ldcg(&g2[(size_t)d * 32 + lane]), dself);
    float4 acc2 = make_float4(0.f, 0.f, 0.f, 0.f);

    int s0 = d_startA[d];
    int cnt = d_counts[d];
    for (int bs = 0; bs < cnt; bs += 32) {
        int rem = cnt - bs;
        int m = rem < 32 ? rem : 32;
        int s = (bs + lane < cnt) ? d_esrc[s0 + bs + lane] : 0;
        int i = 0;
        for (; i + 1 < m; i += 2) {
            int ss0 = __shfl_sync(0xffffffffu, s, i);
            int ss1 = __shfl_sync(0xffffffffu, s, i + 1);
            float dv0 = d_dinv[ss0];
            float dv1 = d_dinv[ss1];
            fma_f4(acc, __ldcg(&g2[(size_t)ss0 * 32 + lane]), dv0);
            fma_f4(acc2, __ldcg(&g2[(size_t)ss1 * 32 + lane]), dv1);
        }
        if (i < m) {
            int ss = __shfl_sync(0xffffffffu, s, i);
            fma_f4(acc, __ldcg(&g2[(size_t)ss * 32 + lane]), d_dinv[ss]);
        }
    }
    acc.x += acc2.x; acc.y += acc2.y; acc.z += acc2.z; acc.w += acc2.w;

    float4 b = ((const float4*)bias)[lane];
    float4 o;
    o.x = tanhf(dself * acc.x + b.x);
    o.y = tanhf(dself * acc.y + b.y);
    o.z = tanhf(dself * acc.z + b.z);
    o.w = tanhf(dself * acc.w + b.w);
    __half2 p0 = __floats2half2_rn(o.x, o.y);
    __half2 p1 = __floats2half2_rn(o.z, o.w);
    uint2 u;
    u.x = *(unsigned*)&p0;
    u.y = *(unsigned*)&p1;
    ((uint2*)hout)[(size_t)d * 32 + lane] = u;
}

// Variant B (layers 1-2, gbuf already dinv-scaled): h = tanh(dinv_d*(g_d + sum g_s)+b)
__global__ void k_aggB(const __half* __restrict__ gbuf, const float* __restrict__ bias,
                       __half* __restrict__ hout, int base, int nn) {
    int d = base + ((blockIdx.x * blockDim.x + threadIdx.x) >> 5);
    if (d >= base + nn || d >= N_NODES) return;
    int lane = threadIdx.x & 31;

    const uint2* g2 = (const uint2*)gbuf;
    float4 acc = h4_to_f4(__ldcg(&g2[(size_t)d * 32 + lane]));
    float4 acc2 = make_float4(0.f, 0.f, 0.f, 0.f);

    int s0 = d_startA[d];
    int cnt = d_counts[d];
    for (int bs = 0; bs < cnt; bs += 32) {
        int rem = cnt - bs;
        int m = rem < 32 ? rem : 32;
        int s = (bs + lane < cnt) ? d_esrc[s0 + bs + lane] : 0;
        int i = 0;
        for (; i + 1 < m; i += 2) {
            int ss0 = __shfl_sync(0xffffffffu, s, i);
            int ss1 = __shfl_sync(0xffffffffu, s, i + 1);
            add_f4(acc, __ldcg(&g2[(size_t)ss0 * 32 + lane]));
            add_f4(acc2, __ldcg(&g2[(size_t)ss1 * 32 + lane]));
        }
        if (i < m) {
            int ss = __shfl_sync(0xffffffffu, s, i);
            add_f4(acc, __ldcg(&g2[(size_t)ss * 32 + lane]));
        }
    }
    acc.x += acc2.x; acc.y += acc2.y; acc.z += acc2.z; acc.w += acc2.w;

    float di = d_dinv[d];
    float4 b = ((const float4*)bias)[lane];
    float4 o;
    o.x = tanhf(di * acc.x + b.x);
    o.y = tanhf(di * acc.y + b.y);
    o.z = tanhf(di * acc.z + b.z);
    o.w = tanhf(di * acc.w + b.w);
    __half2 p0 = __floats2half2_rn(o.x, o.y);
    __half2 p1 = __floats2half2_rn(o.z, o.w);
    uint2 u;
    u.x = *(unsigned*)&p0;
    u.y = *(unsigned*)&p1;
    ((uint2*)hout)[(size_t)d * 32 + lane] = u;
}

// ---------------- head: Wf2(128->32) tanh, Wf3(32->1), per-graph sum --------
// 32 nodes per block (4 tiles of 8). Also resets this chunk's d_counts.
__global__ void k_final(const __half* __restrict__ h2, const float* __restrict__ Wf2,
                        const float* __restrict__ bf2, const float* __restrict__ Wf3,
                        const float* __restrict__ bf3, const int* __restrict__ batch,
                        int base, int nn) {
    __shared__ float Wf2s[128 * 32];
    __shared__ float Hs[8][132];
    __shared__ float bf2s[32];
    __shared__ float wf3s[32];
    int t = threadIdx.x;
    int j = blockIdx.x * 256 + t;
    if (j < nn) d_counts[base + j] = 0;   // reset for next replay
    for (int i = t; i < 128 * 32; i += 256) Wf2s[i] = Wf2[i];
    if (t < 32) { bf2s[t] = bf2[t]; wf3s[t] = Wf3[t]; }

    int lane = t & 31, w = t >> 5;
    int chunkEnd = base + nn;
    float bf3v = __ldg(&bf3[0]);

    for (int it = 0; it < 4; it++) {
        int nodeBase = base + blockIdx.x * 32 + it * 8;
        __syncthreads();
        for (int i = t; i < 8 * 32; i += 256) {
            int r = i >> 5, c4 = i & 31;
            int nd = nodeBase + r;
            uint2 v = make_uint2(0u, 0u);
            if (nd < chunkEnd && nd < N_NODES) v = ((const uint2*)h2)[(size_t)nd * 32 + c4];
            *((float4*)&Hs[r][c4 * 4]) = h4_to_f4(v);
        }
        __syncthreads();

        int node = nodeBase + w;
        if (node < chunkEnd && node < N_NODES) {
            float acc = 0.0f;
#pragma unroll 8
            for (int k = 0; k < 128; k++) acc += Hs[w][k] * Wf2s[k * 32 + lane];
            float tt = tanhf(acc + bf2s[lane]);
            float p = tt * wf3s[lane];
#pragma unroll
            for (int o = 16; o > 0; o >>= 1) p += __shfl_down_sync(0xffffffffu, p, o);
            if (lane == 0) atomicAdd(&d_gsum[batch[node]], p + bf3v);
        }
    }
}

__global__ void k_util(float* __restrict__ out) {
    int g = blockIdx.x * blockDim.x + threadIdx.x;
    if (g < G_GR) {
        float c = (float)d_gcnt[g];
        float u = d_gsum[g] / fmaxf(c, 1.0f);
        d_util[g] = u;
        out[P_PAIRS + g] = u;
        d_gsum[g] = 0.0f;
        d_gcnt[g] = 0;
    }
}

__global__ void k_pairs(const int* __restrict__ ia, const int* __restrict__ ib,
                        float* __restrict__ out) {
    int p = blockIdx.x * blockDim.x + threadIdx.x;
    if (p < P_PAIRS) {
        float x = d_util[ib[p]] - d_util[ia[p]];
        out[p] = 1.0f / (1.0f + expf(-x));
    }
}

// ---------------- launch ----------------------------------------------------
extern "C" void kernel_launch(void* const* d_in, const int* in_sizes, int n_in,
                              void* d_out, int out_size) {
    const float* x     = (const float*)d_in[0];
    const int*   ei    = (const int*)d_in[1];
    const int*   batch = (const int*)d_in[2];
    const int*   idx_a = (const int*)d_in[3];
    const int*   idx_b = (const int*)d_in[4];
    const float* W_in  = (const float*)d_in[5];
    const float* b_in  = (const float*)d_in[6];
    const float* W1    = (const float*)d_in[7];
    const float* b1    = (const float*)d_in[8];
    const float* W2    = (const float*)d_in[9];
    const float* b2    = (const float*)d_in[10];
    const float* Wf1   = (const float*)d_in[11];
    const float* bf1   = (const float*)d_in[12];
    const float* Wf2   = (const float*)d_in[13];
    const float* bf2   = (const float*)d_in[14];
    const float* Wf3   = (const float*)d_in[15];
    const float* bf3   = (const float*)d_in[16];
    float* out = (float*)d_out;

    static __half *pA = nullptr, *pB = nullptr, *pC = nullptr, *pw = nullptr;
    static cudaStream_t s2 = nullptr;
    static cudaEvent_t ev[24];
    if (!pA) {
        cudaGetSymbolAddress((void**)&pA, d_b0);
        cudaGetSymbolAddress((void**)&pB, d_b1);
        cudaGetSymbolAddress((void**)&pC, d_b2);
        cudaGetSymbolAddress((void**)&pw, d_wh);
        cudaFuncSetAttribute(k_gemm_tc<0>, cudaFuncAttributeMaxDynamicSharedMemorySize, 2 * 128 * HSTRIDE * 2);
        cudaFuncSetAttribute(k_gemm_tc<1>, cudaFuncAttributeMaxDynamicSharedMemorySize, 2 * 128 * HSTRIDE * 2);
        cudaStreamCreateWithFlags(&s2, cudaStreamNonBlocking);
        for (int i = 0; i < 24; i++) cudaEventCreateWithFlags(&ev[i], cudaEventDisableTiming);
    }
    const int smem_tc = 2 * 128 * HSTRIDE * 2;   // 69632 B
    const __half* pw0 = pw;
    const __half* pw1 = pw + 128 * HSTRIDE;
    const __half* pw2 = pw + 2 * 128 * HSTRIDE;

    // chunk tables (4 chunks over 100000 nodes)
    static const int cbase[NCHUNK] = {0, 25088, 50176, 75264};
    static const int csize[NCHUNK] = {25088, 25088, 25088, 24736};
    static const int caggb[NCHUNK] = {3136, 3136, 3136, 3092};   // size/8
    static const int cgemb[NCHUNK] = {196, 196, 196, 194};       // ceil(size/128)
    static const int cfinb[NCHUNK] = {784, 784, 784, 773};       // size/32

    // fork: weight prep + layer-0 GEMM overlap CSR build
    cudaEventRecord(ev[0], 0);
    cudaStreamWaitEvent(s2, ev[0], 0);
    k_prepw<<<(3 * 16384 + 255) / 256, 256, 0, s2>>>(W1, W2, Wf1);
    k_gemm_in<<<2048, 128, 0, s2>>>(x, W_in, pA);
    cudaEventRecord(ev[1], s2);

    k_count<<<(E_EDGES / 4 + 255) / 256, 256>>>(ei);
    k_scan1<<<(N_NODES + 1023) / 1024, 1024>>>(N_NODES);
    k_scan3<<<(N_NODES + 255) / 256, 256>>>(batch);
    k_fill<<<(E_EDGES / 4 + 255) / 256, 256>>>(ei);
    cudaStreamWaitEvent(0, ev[1], 0);

    // layer 0: aggA A->B (main), gemm1 B->C (s2, chunk-pipelined)
    for (int c = 0; c < NCHUNK; c++) {
        k_aggA<<<caggb[c], 256>>>(pA, b_in, pB, cbase[c], csize[c]);
        cudaEventRecord(ev[2 + c], 0);
    }
    for (int c = 0; c < NCHUNK; c++) {
        cudaStreamWaitEvent(s2, ev[2 + c], 0);
        k_gemm_tc<0><<<cgemb[c], 256, smem_tc, s2>>>(pB, pw0, nullptr, pC, cbase[c]);
    }
    cudaEventRecord(ev[6], s2);
    cudaStreamWaitEvent(0, ev[6], 0);

    // layer 1: aggB C->A (main), gemm2 A->B (s2)
    for (int c = 0; c < NCHUNK; c++) {
        k_aggB<<<caggb[c], 256>>>(pC, b1, pA, cbase[c], csize[c]);
        cudaEventRecord(ev[7 + c], 0);
    }
    for (int c = 0; c < NCHUNK; c++) {
        cudaStreamWaitEvent(s2, ev[7 + c], 0);
        k_gemm_tc<0><<<cgemb[c], 256, smem_tc, s2>>>(pA, pw1, nullptr, pB, cbase[c]);
    }
    cudaEventRecord(ev[11], s2);
    cudaStreamWaitEvent(0, ev[11], 0);

    // layer 2: aggB B->C (main), head gemm C->A (s2), k_final A (main, chunked)
    for (int c = 0; c < NCHUNK; c++) {
        k_aggB<<<caggb[c], 256>>>(pB, b2, pC, cbase[c], csize[c]);
        cudaEventRecord(ev[12 + c], 0);
    }
    for (int c = 0; c < NCHUNK; c++) {
        cudaStreamWaitEvent(s2, ev[12 + c], 0);
        k_gemm_tc<1><<<cgemb[c], 256, smem_tc, s2>>>(pC, pw2, bf1, pA, cbase[c]);
        cudaEventRecord(ev[16 + c], s2);
    }
    for (int c = 0; c < NCHUNK; c++) {
        cudaStreamWaitEvent(0, ev[16 + c], 0);
        k_final<<<cfinb[c], 256>>>(pA, Wf2, bf2, Wf3, bf3, batch, cbase[c], csize[c]);
    }
    k_util<<<(G_GR + 255) / 256, 256>>>(out);
    k_pairs<<<(P_PAIRS + 255) / 256, 256>>>(idx_a, idx_b, out);
}

// round 10
// speedup vs baseline: 1.1474x; 1.1474x over previous
#include <cuda_runtime.h>
#include <cuda_fp16.h>
#include <math.h>

#define N_NODES 100000
#define E_EDGES 1600000
#define G_GR    2000
#define P_PAIRS 4096
#define UDIM    128
#define HSTRIDE 136

// ---------------- scratch (static device globals; no allocation) -------------
// Globals start zeroed; each run re-zeroes what it dirties (d_counts in
// k_final, d_gsum/d_gcnt in k_util) so graph replays stay deterministic.
__device__ __half d_b0[N_NODES * UDIM];    // ping
__device__ __half d_b1[N_NODES * UDIM];    // pong
__device__ __half d_wh[3 * 128 * HSTRIDE]; // pre-transposed fp16 weights (n,k)
__device__ int    d_counts[N_NODES];
__device__ int    d_startA[N_NODES];
__device__ int    d_cursor[N_NODES];
__device__ int    d_bsums[128];
__device__ float  d_dinv[N_NODES];
__device__ int    d_esrc[E_EDGES];         // edge srcs sorted by dst
__device__ float  d_gsum[G_GR];
__device__ int    d_gcnt[G_GR];
__device__ float  d_util[G_GR];

// ---------------- helpers ----------------------------------------------------
__device__ __forceinline__ float4 h4_to_f4(uint2 u) {
    __half2 p0 = *(__half2*)&u.x;
    __half2 p1 = *(__half2*)&u.y;
    float2 f0 = __half22float2(p0), f1 = __half22float2(p1);
    return make_float4(f0.x, f0.y, f1.x, f1.y);
}
__device__ __forceinline__ void add_f4(float4& a, uint2 u) {
    float2 x = __half22float2(*(__half2*)&u.x);
    float2 y = __half22float2(*(__half2*)&u.y);
    a.x += x.x; a.y += x.y; a.z += y.x; a.w += y.y;
}
__device__ __forceinline__ void fma_f4(float4& a, uint2 u, float s) {
    float2 x = __half22float2(*(__half2*)&u.x);
    float2 y = __half22float2(*(__half2*)&u.y);
    a.x = fmaf(s, x.x, a.x); a.y = fmaf(s, x.y, a.y);
    a.z = fmaf(s, y.x, a.z); a.w = fmaf(s, y.y, a.w);
}

// ---------------- CSR build --------------------------------------------------
__global__ void k_count(const int* __restrict__ ei) {
    int e = blockIdx.x * blockDim.x + threadIdx.x;
    if (e < E_EDGES / 4) {
        int4 d4 = __ldg((const int4*)(ei + E_EDGES) + e);
        atomicAdd(&d_counts[d4.x], 1);
        atomicAdd(&d_counts[d4.y], 1);
        atomicAdd(&d_counts[d4.z], 1);
        atomicAdd(&d_counts[d4.w], 1);
    }
}

__global__ void k_scan1(int n) {
    __shared__ int wsum[32];
    int i = blockIdx.x * 1024 + threadIdx.x;
    int lane = threadIdx.x & 31, w = threadIdx.x >> 5;
    int v = (i < n) ? d_counts[i] : 0;
    int x = v;
#pragma unroll
    for (int o = 1; o < 32; o <<= 1) {
        int y = __shfl_up_sync(0xffffffffu, x, o);
        if (lane >= o) x += y;
    }
    if (lane == 31) wsum[w] = x;
    __syncthreads();
    if (w == 0) {
        int s = wsum[lane];
        int xx = s;
#pragma unroll
        for (int o = 1; o < 32; o <<= 1) {
            int y = __shfl_up_sync(0xffffffffu, xx, o);
            if (lane >= o) xx += y;
        }
        if (lane == 31) d_bsums[blockIdx.x] = xx;
        wsum[lane] = xx - s;
    }
    __syncthreads();
    int excl = x - v + wsum[w];
    if (i < n) d_startA[i] = excl;
}

__global__ void k_scan3(const int* __restrict__ batch) {
    __shared__ int soff;
    int i = blockIdx.x * 256 + threadIdx.x;
    int tile = (blockIdx.x * 256) >> 10;
    if (threadIdx.x < 32) {
        int lane = threadIdx.x;
        int s = 0;
        for (int j = lane; j < tile; j += 32) s += d_bsums[j];
#pragma unroll
        for (int o = 16; o > 0; o >>= 1) s += __shfl_xor_sync(0xffffffffu, s, o);
        if (lane == 0) soff = s;
    }
    __syncthreads();
    if (i < N_NODES) {
        int sA = d_startA[i] + soff;
        d_startA[i] = sA;
        d_cursor[i] = sA;
        d_dinv[i] = rsqrtf((float)d_counts[i] + 1.0f);
        atomicAdd(&d_gcnt[__ldg(&batch[i])], 1);
    }
}

__global__ void k_fill(const int* __restrict__ ei) {
    int e = blockIdx.x * blockDim.x + threadIdx.x;
    if (e < E_EDGES / 4) {
        int4 s4 = __ldg((const int4*)ei + e);
        int4 t4 = __ldg((const int4*)(ei + E_EDGES) + e);
        d_esrc[atomicAdd(&d_cursor[t4.x], 1)] = s4.x;
        d_esrc[atomicAdd(&d_cursor[t4.y], 1)] = s4.y;
        d_esrc[atomicAdd(&d_cursor[t4.z], 1)] = s4.z;
        d_esrc[atomicAdd(&d_cursor[t4.w], 1)] = s4.w;
    }
}

// pre-transpose three 128x128 fp32 weights -> fp16 (n,k) padded HSTRIDE
__global__ void k_prepw(const float* __restrict__ W0, const float* __restrict__ W1,
                        const float* __restrict__ W2) {
    int tid = blockIdx.x * blockDim.x + threadIdx.x;
    if (tid >= 3 * 16384) return;
    int m = tid >> 14, r = tid & 16383;
    int k = r >> 7, n = r & 127;
    const float* W = (m == 0) ? W0 : (m == 1) ? W1 : W2;
    d_wh[m * 128 * HSTRIDE + n * HSTRIDE + k] = __float2half(W[k * 128 + n]);
}

// ---------------- GEMMs -----------------------------------------------------
// layer 0: y = x[N,9] @ W_in[9,128] (raw, no dinv) -> fp16
__global__ void k_gemm_in(const float* __restrict__ x, const float* __restrict__ W,
                          __half* __restrict__ g) {
    __shared__ float Ws[9 * 128];
    for (int i = threadIdx.x; i < 9 * 128; i += 128) Ws[i] = W[i];
    __syncthreads();
    int j = threadIdx.x;
    for (int row = blockIdx.x; row < N_NODES; row += gridDim.x) {
        float acc = 0.0f;
#pragma unroll
        for (int k = 0; k < 9; k++)
            acc += __ldg(&x[row * 9 + k]) * Ws[k * 128 + j];
        g[row * 128 + j] = __float2half(acc);
    }
}

// fp16 TC GEMM. MODE 0: C = dinv*(A@W)   MODE 1: C = tanh(A@W + bias)
template <int MODE>
__global__ __launch_bounds__(256) void k_gemm_tc(
        const __half* __restrict__ A, const __half* __restrict__ Wt_g,
        const float* __restrict__ bias, __half* __restrict__ C) {
    extern __shared__ __half sm[];
    __half* As = sm;                  // [128][136] (row, k)
    __half* Wt = sm + 128 * HSTRIDE;  // [128][136] (n, k)
    const int t = threadIdx.x;
    const int row0 = blockIdx.x * 128;

    const uint4* Wg4 = (const uint4*)Wt_g;
    uint4* Wt4 = (uint4*)Wt;
    for (int i = t; i < 128 * 17; i += 256) Wt4[i] = Wg4[i];

    const uint4* A4 = (const uint4*)A;
    for (int i = t; i < 128 * 16; i += 256) {
        int r = i >> 4, c = i & 15;
        uint4 v = make_uint4(0u, 0u, 0u, 0u);
        if (row0 + r < N_NODES) v = A4[(size_t)(row0 + r) * 16 + c];
        *(uint4*)&As[r * HSTRIDE + c * 8] = v;
    }
    __syncthreads();

    const int w = t >> 5, lane = t & 31;
    const int wm = w & 3, wn = w >> 2;
    const int rbase = wm * 32;
    const int cbase = wn * 64;
    const int gid = lane >> 2, tig = lane & 3;

    float acc[2][8][4];
#pragma unroll
    for (int mi = 0; mi < 2; mi++)
#pragma unroll
        for (int ni = 0; ni < 8; ni++)
#pragma unroll
            for (int q = 0; q < 4; q++) acc[mi][ni][q] = 0.0f;

#pragma unroll
    for (int ks = 0; ks < 8; ks++) {
        const int k0 = ks * 16;
        unsigned a[2][4];
#pragma unroll
        for (int mi = 0; mi < 2; mi++) {
            int r = rbase + mi * 16 + gid;
            a[mi][0] = *(const unsigned*)&As[r * HSTRIDE + k0 + tig * 2];
            a[mi][1] = *(const unsigned*)&As[(r + 8) * HSTRIDE + k0 + tig * 2];
            a[mi][2] = *(const unsigned*)&As[r * HSTRIDE + k0 + 8 + tig * 2];
            a[mi][3] = *(const unsigned*)&As[(r + 8) * HSTRIDE + k0 + 8 + tig * 2];
        }
        unsigned b[8][2];
#pragma unroll
        for (int ni = 0; ni < 8; ni++) {
            int n = cbase + ni * 8 + gid;
            b[ni][0] = *(const unsigned*)&Wt[n * HSTRIDE + k0 + tig * 2];
            b[ni][1] = *(const unsigned*)&Wt[n * HSTRIDE + k0 + 8 + tig * 2];
        }
#pragma unroll
        for (int mi = 0; mi < 2; mi++)
#pragma unroll
            for (int ni = 0; ni < 8; ni++)
                asm volatile(
                    "mma.sync.aligned.m16n8k16.row.col.f32.f16.f16.f32 "
                    "{%0,%1,%2,%3}, {%4,%5,%6,%7}, {%8,%9}, {%0,%1,%2,%3};"
                    : "+f"(acc[mi][ni][0]), "+f"(acc[mi][ni][1]),
                      "+f"(acc[mi][ni][2]), "+f"(acc[mi][ni][3])
                    : "r"(a[mi][0]), "r"(a[mi][1]), "r"(a[mi][2]), "r"(a[mi][3]),
                      "r"(b[ni][0]), "r"(b[ni][1]));
    }

#pragma unroll
    for (int mi = 0; mi < 2; mi++) {
#pragma unroll
        for (int hf = 0; hf < 2; hf++) {
            int r = row0 + rbase + mi * 16 + gid + hf * 8;
            if (r < N_NODES) {
                float scale = (MODE == 0) ? d_dinv[r] : 1.0f;
#pragma unroll
                for (int ni = 0; ni < 8; ni++) {
                    int c = cbase + ni * 8 + tig * 2;
                    float v0 = acc[mi][ni][hf * 2 + 0];
                    float v1 = acc[mi][ni][hf * 2 + 1];
                    if (MODE == 0) { v0 *= scale; v1 *= scale; }
                    else {
                        v0 = tanhf(v0 + __ldg(&bias[c]));
                        v1 = tanhf(v1 + __ldg(&bias[c + 1]));
                    }
                    *(__half2*)&C[(size_t)r * 128 + c] = __floats2half2_rn(v0, v1);
                }
            }
        }
    }
}

// ---------------- edge aggregation ------------------------------------------
// Variant A (layer 0, raw y): h = tanh(dinv_d*(dinv_d*y_d + sum dinv_s*y_s)+b)
__global__ void k_aggA(const __half* __restrict__ gbuf, const float* __restrict__ bias,
                       __half* __restrict__ hout) {
    int d = (blockIdx.x * blockDim.x + threadIdx.x) >> 5;
    if (d >= N_NODES) return;
    int lane = threadIdx.x & 31;

    const uint2* g2 = (const uint2*)gbuf;
    float dself = d_dinv[d];
    float4 acc = make_float4(0.f, 0.f, 0.f, 0.f);
    fma_f4(acc, __ldcg(&g2[(size_t)d * 32 + lane]), dself);
    float4 acc2 = make_float4(0.f, 0.f, 0.f, 0.f);

    int s0 = d_startA[d];
    int cnt = d_counts[d];
    for (int bs = 0; bs < cnt; bs += 32) {
        int rem = cnt - bs;
        int m = rem < 32 ? rem : 32;
        int s = (bs + lane < cnt) ? d_esrc[s0 + bs + lane] : 0;
        int i = 0;
        for (; i + 1 < m; i += 2) {
            int ss0 = __shfl_sync(0xffffffffu, s, i);
            int ss1 = __shfl_sync(0xffffffffu, s, i + 1);
            float dv0 = d_dinv[ss0];
            float dv1 = d_dinv[ss1];
            fma_f4(acc, __ldcg(&g2[(size_t)ss0 * 32 + lane]), dv0);
            fma_f4(acc2, __ldcg(&g2[(size_t)ss1 * 32 + lane]), dv1);
        }
        if (i < m) {
            int ss = __shfl_sync(0xffffffffu, s, i);
            fma_f4(acc, __ldcg(&g2[(size_t)ss * 32 + lane]), d_dinv[ss]);
        }
    }
    acc.x += acc2.x; acc.y += acc2.y; acc.z += acc2.z; acc.w += acc2.w;

    float4 b = ((const float4*)bias)[lane];
    float4 o;
    o.x = tanhf(dself * acc.x + b.x);
    o.y = tanhf(dself * acc.y + b.y);
    o.z = tanhf(dself * acc.z + b.z);
    o.w = tanhf(dself * acc.w + b.w);
    __half2 p0 = __floats2half2_rn(o.x, o.y);
    __half2 p1 = __floats2half2_rn(o.z, o.w);
    uint2 u;
    u.x = *(unsigned*)&p0;
    u.y = *(unsigned*)&p1;
    ((uint2*)hout)[(size_t)d * 32 + lane] = u;
}

// Variant B (layers 1-2, gbuf already dinv-scaled): h = tanh(dinv_d*(g_d + sum g_s)+b)
__global__ void k_aggB(const __half* __restrict__ gbuf, const float* __restrict__ bias,
                       __half* __restrict__ hout) {
    int d = (blockIdx.x * blockDim.x + threadIdx.x) >> 5;
    if (d >= N_NODES) return;
    int lane = threadIdx.x & 31;

    const uint2* g2 = (const uint2*)gbuf;
    float4 acc = h4_to_f4(__ldcg(&g2[(size_t)d * 32 + lane]));
    float4 acc2 = make_float4(0.f, 0.f, 0.f, 0.f);

    int s0 = d_startA[d];
    int cnt = d_counts[d];
    for (int bs = 0; bs < cnt; bs += 32) {
        int rem = cnt - bs;
        int m = rem < 32 ? rem : 32;
        int s = (bs + lane < cnt) ? d_esrc[s0 + bs + lane] : 0;
        int i = 0;
        for (; i + 1 < m; i += 2) {
            int ss0 = __shfl_sync(0xffffffffu, s, i);
            int ss1 = __shfl_sync(0xffffffffu, s, i + 1);
            add_f4(acc, __ldcg(&g2[(size_t)ss0 * 32 + lane]));
            add_f4(acc2, __ldcg(&g2[(size_t)ss1 * 32 + lane]));
        }
        if (i < m) {
            int ss = __shfl_sync(0xffffffffu, s, i);
            add_f4(acc, __ldcg(&g2[(size_t)ss * 32 + lane]));
        }
    }
    acc.x += acc2.x; acc.y += acc2.y; acc.z += acc2.z; acc.w += acc2.w;

    float di = d_dinv[d];
    float4 b = ((const float4*)bias)[lane];
    float4 o;
    o.x = tanhf(di * acc.x + b.x);
    o.y = tanhf(di * acc.y + b.y);
    o.z = tanhf(di * acc.z + b.z);
    o.w = tanhf(di * acc.w + b.w);
    __half2 p0 = __floats2half2_rn(o.x, o.y);
    __half2 p1 = __floats2half2_rn(o.z, o.w);
    uint2 u;
    u.x = *(unsigned*)&p0;
    u.y = *(unsigned*)&p1;
    ((uint2*)hout)[(size_t)d * 32 + lane] = u;
}

// ---------------- head: Wf2(128->32) tanh, Wf3(32->1), per-graph sum --------
// 32 nodes per block (4 tiles of 8); also resets d_counts for next replay.
__global__ void k_final(const __half* __restrict__ h2, const float* __restrict__ Wf2,
                        const float* __restrict__ bf2, const float* __restrict__ Wf3,
                        const float* __restrict__ bf3, const int* __restrict__ batch) {
    __shared__ float Wf2s[128 * 32];
    __shared__ float Hs[8][132];
    __shared__ float bf2s[32];
    __shared__ float wf3s[32];
    int t = threadIdx.x;
    int gtid = blockIdx.x * 256 + t;
    if (gtid < N_NODES) d_counts[gtid] = 0;   // reset for next replay
    for (int i = t; i < 128 * 32; i += 256) Wf2s[i] = Wf2[i];
    if (t < 32) { bf2s[t] = bf2[t]; wf3s[t] = Wf3[t]; }

    int lane = t & 31, w = t >> 5;
    float bf3v = __ldg(&bf3[0]);

    for (int it = 0; it < 4; it++) {
        int nodeBase = blockIdx.x * 32 + it * 8;
        __syncthreads();
        for (int i = t; i < 8 * 32; i += 256) {
            int r = i >> 5, c4 = i & 31;
            int nd = nodeBase + r;
            uint2 v = make_uint2(0u, 0u);
            if (nd < N_NODES) v = ((const uint2*)h2)[(size_t)nd * 32 + c4];
            *((float4*)&Hs[r][c4 * 4]) = h4_to_f4(v);
        }
        __syncthreads();

        int node = nodeBase + w;
        if (node < N_NODES) {
            float acc = 0.0f;
#pragma unroll 8
            for (int k = 0; k < 128; k++) acc += Hs[w][k] * Wf2s[k * 32 + lane];
            float tt = tanhf(acc + bf2s[lane]);
            float p = tt * wf3s[lane];
#pragma unroll
            for (int o = 16; o > 0; o >>= 1) p += __shfl_down_sync(0xffffffffu, p, o);
            if (lane == 0) atomicAdd(&d_gsum[batch[node]], p + bf3v);
        }
    }
}

__global__ void k_util(float* __restrict__ out) {
    int g = blockIdx.x * blockDim.x + threadIdx.x;
    if (g < G_GR) {
        float c = (float)d_gcnt[g];
        float u = d_gsum[g] / fmaxf(c, 1.0f);
        d_util[g] = u;
        out[P_PAIRS + g] = u;
        d_gsum[g] = 0.0f;
        d_gcnt[g] = 0;
    }
}

__global__ void k_pairs(const int* __restrict__ ia, const int* __restrict__ ib,
                        float* __restrict__ out) {
    int p = blockIdx.x * blockDim.x + threadIdx.x;
    if (p < P_PAIRS) {
        float x = d_util[ib[p]] - d_util[ia[p]];
        out[p] = 1.0f / (1.0f + expf(-x));
    }
}

// ---------------- launch ----------------------------------------------------
extern "C" void kernel_launch(void* const* d_in, const int* in_sizes, int n_in,
                              void* d_out, int out_size) {
    const float* x     = (const float*)d_in[0];
    const int*   ei    = (const int*)d_in[1];
    const int*   batch = (const int*)d_in[2];
    const int*   idx_a = (const int*)d_in[3];
    const int*   idx_b = (const int*)d_in[4];
    const float* W_in  = (const float*)d_in[5];
    const float* b_in  = (const float*)d_in[6];
    const float* W1    = (const float*)d_in[7];
    const float* b1    = (const float*)d_in[8];
    const float* W2    = (const float*)d_in[9];
    const float* b2    = (const float*)d_in[10];
    const float* Wf1   = (const float*)d_in[11];
    const float* bf1   = (const float*)d_in[12];
    const float* Wf2   = (const float*)d_in[13];
    const float* bf2   = (const float*)d_in[14];
    const float* Wf3   = (const float*)d_in[15];
    const float* bf3   = (const float*)d_in[16];
    float* out = (float*)d_out;

    static __half *pA = nullptr, *pB = nullptr, *pw = nullptr;
    static cudaStream_t s2 = nullptr;
    static cudaEvent_t evF = nullptr, evJ = nullptr;
    if (!pA) {
        cudaGetSymbolAddress((void**)&pA, d_b0);
        cudaGetSymbolAddress((void**)&pB, d_b1);
        cudaGetSymbolAddress((void**)&pw, d_wh);
        cudaFuncSetAttribute(k_gemm_tc<0>, cudaFuncAttributeMaxDynamicSharedMemorySize, 2 * 128 * HSTRIDE * 2);
        cudaFuncSetAttribute(k_gemm_tc<1>, cudaFuncAttributeMaxDynamicSharedMemorySize, 2 * 128 * HSTRIDE * 2);
        cudaStreamCreateWithFlags(&s2, cudaStreamNonBlocking);
        cudaEventCreateWithFlags(&evF, cudaEventDisableTiming);
        cudaEventCreateWithFlags(&evJ, cudaEventDisableTiming);
    }
    const int smem_tc = 2 * 128 * HSTRIDE * 2;   // 69632 B
    const __half* pw0 = pw;
    const __half* pw1 = pw + 128 * HSTRIDE;
    const __half* pw2 = pw + 2 * 128 * HSTRIDE;

    const int tc_grid  = (N_NODES + 127) / 128;  // 782
    const int agg_grid = (N_NODES + 7) / 8;      // 12500
    const int fin_grid = (N_NODES + 31) / 32;    // 3125

    // fork: weight prep + layer-0 GEMM overlap CSR build
    cudaEventRecord(evF, 0);
    cudaStreamWaitEvent(s2, evF, 0);
    k_prepw<<<(3 * 16384 + 255) / 256, 256, 0, s2>>>(W1, W2, Wf1);
    k_gemm_in<<<2048, 128, 0, s2>>>(x, W_in, pA);
    cudaEventRecord(evJ, s2);

    k_count<<<(E_EDGES / 4 + 255) / 256, 256>>>(ei);
    k_scan1<<<(N_NODES + 1023) / 1024, 1024>>>(N_NODES);
    k_scan3<<<(N_NODES + 255) / 256, 256>>>(batch);
    k_fill<<<(E_EDGES / 4 + 255) / 256, 256>>>(ei);
    cudaStreamWaitEvent(0, evJ, 0);

    // layer 0
    k_aggA<<<agg_grid, 256>>>(pA, b_in, pB);
    // layer 1 (gemm scales by dinv -> aggB)
    k_gemm_tc<0><<<tc_grid, 256, smem_tc>>>(pB, pw0, nullptr, pA);
    k_aggB<<<agg_grid, 256>>>(pA, b1, pB);
    // layer 2
    k_gemm_tc<0><<<tc_grid, 256, smem_tc>>>(pB, pw1, nullptr, pA);
    k_aggB<<<agg_grid, 256>>>(pA, b2, pB);
    // head
    k_gemm_tc<1><<<tc_grid, 256, smem_tc>>>(pB, pw2, bf1, pA);
    k_final<<<fin_grid, 256>>>(pA, Wf2, bf2, Wf3, bf3, batch);
    k_util<<<(G_GR + 255) / 256, 256>>>(out);
    k_pairs<<<(P_PAIRS + 255) / 256, 256>>>(idx_a, idx_b, out);
}